// round 7
// baseline (speedup 1.0000x reference)
#include <cuda_runtime.h>
#include <cuda_fp16.h>
#include <cstddef>

#define N_NODES_MAX 50000
#define N_EDGES_MAX 800000
#define IN_CH 128
#define HID 64
#define SCAN_B 1024

// ---------------- device scratch (no allocation allowed) ----------------
__device__ int    g_deg[N_NODES_MAX];
__device__ int    g_cursor[N_NODES_MAX];
__device__ int    g_row[N_NODES_MAX + 1];
__device__ float  g_dinv[N_NODES_MAX];
__device__ int    g_col[N_EDGES_MAX];          // src ids grouped by dst
__device__ int    g_bsum[(N_NODES_MAX + SCAN_B - 1) / SCAN_B + 1];
__device__ int    g_ready;                     // lookback counter (memset to 0)
__device__ __half g_P[N_NODES_MAX * 64];       // fp16 projection buffer (both layers)
__device__ float  g_H[N_NODES_MAX * 64];       // fp32 hidden activations

// ---------------- CSR build ----------------
// 4 edges per thread: 2x grid size vs 8/thread -> ~66% occupancy, more atomics in flight
__global__ void count_deg_kernel(const int* __restrict__ dst, int n_edges) {
    int i0 = (blockIdx.x * blockDim.x + threadIdx.x) * 4;
    if (i0 + 4 <= n_edges) {
        int4 a = *reinterpret_cast<const int4*>(dst + i0);
        atomicAdd(&g_deg[a.x], 1); atomicAdd(&g_deg[a.y], 1);
        atomicAdd(&g_deg[a.z], 1); atomicAdd(&g_deg[a.w], 1);
    } else {
        for (int j = 0; j < 4 && i0 + j < n_edges; j++)
            atomicAdd(&g_deg[dst[i0 + j]], 1);
    }
}

__device__ __forceinline__ int block_scan_incl(int v, int* warp_sums) {
    int lane = threadIdx.x & 31;
    int wid = threadIdx.x >> 5;
    int x = v;
    #pragma unroll
    for (int off = 1; off < 32; off <<= 1) {
        int y = __shfl_up_sync(0xFFFFFFFFu, x, off);
        if (lane >= off) x += y;
    }
    if (lane == 31) warp_sums[wid] = x;
    __syncthreads();
    if (wid == 0) {
        int w = warp_sums[lane];
        #pragma unroll
        for (int off = 1; off < 32; off <<= 1) {
            int y = __shfl_up_sync(0xFFFFFFFFu, w, off);
            if (lane >= off) w += y;
        }
        warp_sums[lane] = w;
    }
    __syncthreads();
    return x + ((wid > 0) ? warp_sums[wid - 1] : 0);
}

// Single-pass scan with grid-resident counter wait (49 blocks << 148 SMs).
__global__ void __launch_bounds__(SCAN_B) scan_fused_kernel(int n, int E) {
    __shared__ int warp_sums[32];
    __shared__ int s_off;
    int b = blockIdx.x;
    int i = b * SCAN_B + threadIdx.x;
    int v = (i < n) ? g_deg[i] : 0;
    int incl = block_scan_incl(v, warp_sums);

    if (threadIdx.x == 0) {
        g_bsum[b] = warp_sums[31];
        __threadfence();
        atomicAdd(&g_ready, 1);
        while (atomicAdd(&g_ready, 0) < (int)gridDim.x) {}
        __threadfence();
        int s = 0;
        for (int j = 0; j < b; j++) s += g_bsum[j];
        s_off = s;
    }
    __syncthreads();

    if (i < n) {
        int r = incl - v + s_off;
        g_row[i] = r;
        g_cursor[i] = r;
        g_dinv[i] = rsqrtf((float)v + 1.0f);  // deg incl. self-loop
    }
    if (b == 0 && threadIdx.x == 0) g_row[n] = E;
}

__global__ void fill_edges_kernel(const int* __restrict__ src,
                                  const int* __restrict__ dst, int n_edges) {
    int i0 = (blockIdx.x * blockDim.x + threadIdx.x) * 4;
    if (i0 + 4 <= n_edges) {
        int4 d = *reinterpret_cast<const int4*>(dst + i0);
        int4 s = *reinterpret_cast<const int4*>(src + i0);
        int p0 = atomicAdd(&g_cursor[d.x], 1);
        int p1 = atomicAdd(&g_cursor[d.y], 1);
        int p2 = atomicAdd(&g_cursor[d.z], 1);
        int p3 = atomicAdd(&g_cursor[d.w], 1);
        g_col[p0] = s.x; g_col[p1] = s.y; g_col[p2] = s.z; g_col[p3] = s.w;
    } else {
        for (int j = 0; j < 4 && i0 + j < n_edges; j++) {
            int p = atomicAdd(&g_cursor[dst[i0 + j]], 1);
            g_col[p] = src[i0 + j];
        }
    }
}

// scale P rows by dinv: P'[i] = dinv[i] * P[i]  (fp32 mul, one half-round)
__global__ void scale_P_kernel(__half* __restrict__ P, int n) {
    int t = blockIdx.x * blockDim.x + threadIdx.x;
    int node = t >> 3;
    if (node >= n) return;
    int l = t & 7;
    float di = g_dinv[node];
    uint4 v = reinterpret_cast<uint4*>(P)[(size_t)node * 8 + l];
    __half2* hp = reinterpret_cast<__half2*>(&v);
    #pragma unroll
    for (int j = 0; j < 4; j++) {
        float2 f = __half22float2(hp[j]);
        hp[j] = __floats2half2_rn(f.x * di, f.y * di);
    }
    reinterpret_cast<uint4*>(P)[(size_t)node * 8 + l] = v;
}

// ---------------- dense GEMM: Y[n,64](fp16) = scale? dinv[row]* (X[n,K] @ W[K,64]) ----------------
template <int K, bool SCALE_DINV>
__global__ void __launch_bounds__(128) gemm128_kernel(const float* __restrict__ X,
                                                      const float* __restrict__ W,
                                                      __half* __restrict__ Y, int n) {
    const int KC = 32;
    __shared__ float Xs[KC][132];
    __shared__ float Ws[KC][68];

    int t = threadIdx.x;
    int row0 = blockIdx.x * 128;
    int ty = t >> 3;   // 0..15 -> 8 rows each
    int tx = t & 7;    // 0..7  -> 8 cols each

    float acc[8][8];
    #pragma unroll
    for (int i = 0; i < 8; i++)
        #pragma unroll
        for (int j = 0; j < 8; j++) acc[i][j] = 0.0f;

    for (int kc = 0; kc < K; kc += KC) {
        #pragma unroll
        for (int u = 0; u < 8; u++) {
            int idx = t + u * 128;
            int r = idx >> 3;
            int q = idx & 7;
            int row = row0 + r;
            if (row >= n) row = n - 1;
            float4 v = *reinterpret_cast<const float4*>(X + (size_t)row * K + kc + q * 4);
            Xs[q * 4 + 0][r] = v.x;
            Xs[q * 4 + 1][r] = v.y;
            Xs[q * 4 + 2][r] = v.z;
            Xs[q * 4 + 3][r] = v.w;
        }
        #pragma unroll
        for (int u = 0; u < 4; u++) {
            int idx = t + u * 128;
            int kk = idx >> 4;
            int q = idx & 15;
            float4 v = *reinterpret_cast<const float4*>(W + (size_t)(kc + kk) * 64 + q * 4);
            *reinterpret_cast<float4*>(&Ws[kk][q * 4]) = v;
        }
        __syncthreads();

        #pragma unroll 8
        for (int kk = 0; kk < KC; kk++) {
            float a[8], b[8];
            *reinterpret_cast<float4*>(a)     = *reinterpret_cast<const float4*>(&Xs[kk][ty * 8]);
            *reinterpret_cast<float4*>(a + 4) = *reinterpret_cast<const float4*>(&Xs[kk][ty * 8 + 4]);
            *reinterpret_cast<float4*>(b)     = *reinterpret_cast<const float4*>(&Ws[kk][tx * 8]);
            *reinterpret_cast<float4*>(b + 4) = *reinterpret_cast<const float4*>(&Ws[kk][tx * 8 + 4]);
            #pragma unroll
            for (int i = 0; i < 8; i++)
                #pragma unroll
                for (int j = 0; j < 8; j++)
                    acc[i][j] += a[i] * b[j];
        }
        __syncthreads();
    }

    #pragma unroll
    for (int i = 0; i < 8; i++) {
        int row = row0 + ty * 8 + i;
        if (row < n) {
            float sc = SCALE_DINV ? g_dinv[row] : 1.0f;
            __half2 h[4];
            #pragma unroll
            for (int j = 0; j < 4; j++)
                h[j] = __floats2half2_rn(acc[i][2 * j] * sc, acc[i][2 * j + 1] * sc);
            *reinterpret_cast<uint4*>(Y + (size_t)row * 64 + tx * 8) =
                *reinterpret_cast<const uint4*>(h);
        }
    }
}

// ---------------- aggregation on pre-scaled P': out = dinv[d]*(ΣP'[src] + P'[d]) + b ----------------
template <bool RELU>
__global__ void __launch_bounds__(256) spmm64_kernel(const __half* __restrict__ P,
                                                     const float* __restrict__ bias,
                                                     float* __restrict__ Y, int n) {
    int t = blockIdx.x * blockDim.x + threadIdx.x;
    int node = t >> 3;
    if (node >= n) return;
    int l = t & 7;

    const uint4* Pv = reinterpret_cast<const uint4*>(P);
    float di = g_dinv[node];

    float acc[8];
    {
        uint4 v = Pv[(size_t)node * 8 + l];   // self-loop term P'[node]
        const __half2* hp = reinterpret_cast<const __half2*>(&v);
        #pragma unroll
        for (int j = 0; j < 4; j++) {
            float2 f = __half22float2(hp[j]);
            acc[2 * j]     = f.x;
            acc[2 * j + 1] = f.y;
        }
    }

    int e = g_row[node];
    int end = g_row[node + 1];
    for (; e + 4 <= end; e += 4) {
        int s0 = g_col[e], s1 = g_col[e + 1], s2 = g_col[e + 2], s3 = g_col[e + 3];
        uint4 v0 = Pv[(size_t)s0 * 8 + l];
        uint4 v1 = Pv[(size_t)s1 * 8 + l];
        uint4 v2 = Pv[(size_t)s2 * 8 + l];
        uint4 v3 = Pv[(size_t)s3 * 8 + l];
        const __half2* h0 = reinterpret_cast<const __half2*>(&v0);
        const __half2* h1 = reinterpret_cast<const __half2*>(&v1);
        const __half2* h2 = reinterpret_cast<const __half2*>(&v2);
        const __half2* h3 = reinterpret_cast<const __half2*>(&v3);
        #pragma unroll
        for (int j = 0; j < 4; j++) {
            float2 f0 = __half22float2(h0[j]);
            float2 f1 = __half22float2(h1[j]);
            float2 f2 = __half22float2(h2[j]);
            float2 f3 = __half22float2(h3[j]);
            acc[2 * j]     += (f0.x + f1.x) + (f2.x + f3.x);
            acc[2 * j + 1] += (f0.y + f1.y) + (f2.y + f3.y);
        }
    }
    for (; e < end; e++) {
        int s0 = g_col[e];
        uint4 v0 = Pv[(size_t)s0 * 8 + l];
        const __half2* h0 = reinterpret_cast<const __half2*>(&v0);
        #pragma unroll
        for (int j = 0; j < 4; j++) {
            float2 f0 = __half22float2(h0[j]);
            acc[2 * j]     += f0.x;
            acc[2 * j + 1] += f0.y;
        }
    }

    float4 b0 = reinterpret_cast<const float4*>(bias)[l * 2];
    float4 b1 = reinterpret_cast<const float4*>(bias)[l * 2 + 1];
    acc[0] = acc[0] * di + b0.x; acc[1] = acc[1] * di + b0.y;
    acc[2] = acc[2] * di + b0.z; acc[3] = acc[3] * di + b0.w;
    acc[4] = acc[4] * di + b1.x; acc[5] = acc[5] * di + b1.y;
    acc[6] = acc[6] * di + b1.z; acc[7] = acc[7] * di + b1.w;
    if (RELU) {
        #pragma unroll
        for (int j = 0; j < 8; j++) acc[j] = fmaxf(acc[j], 0.0f);
    }
    float4* Yo = reinterpret_cast<float4*>(Y + (size_t)node * 64 + l * 8);
    Yo[0] = make_float4(acc[0], acc[1], acc[2], acc[3]);
    Yo[1] = make_float4(acc[4], acc[5], acc[6], acc[7]);
}

// ---------------- launcher ----------------
extern "C" void kernel_launch(void* const* d_in, const int* in_sizes, int n_in,
                              void* d_out, int out_size) {
    const float* x  = (const float*)d_in[0];       // [n, 128]
    const int*   ei = (const int*)d_in[1];         // [2, E]
    const float* W1 = (const float*)d_in[2];       // [128, 64]
    const float* b1 = (const float*)d_in[3];       // [64]
    const float* W2 = (const float*)d_in[4];       // [64, 64]
    const float* b2 = (const float*)d_in[5];       // [64]
    float* out = (float*)d_out;                    // [n, 64]

    int n = in_sizes[0] / IN_CH;
    int E = in_sizes[1] / 2;
    const int* src = ei;
    const int* dst = ei + E;

    void* p;
    cudaGetSymbolAddress(&p, g_P);
    __half* P = (__half*)p;
    cudaGetSymbolAddress(&p, g_H);
    float* H = (float*)p;
    void* deg_ptr;
    cudaGetSymbolAddress(&deg_ptr, g_deg);
    void* ready_ptr;
    cudaGetSymbolAddress(&ready_ptr, g_ready);

    int nb = (n + SCAN_B - 1) / SCAN_B;
    int eb4 = (E + 4 * 256 - 1) / (4 * 256);
    int spmm_blocks = (n * 8 + 255) / 256;
    int gemm_blocks = (n + 127) / 128;

    // Fork side stream: CSR build overlaps GEMM1. (Host objects leak by design;
    // destroying capture-participating streams/events mid-capture is illegal.)
    cudaStream_t s2;
    cudaStreamCreateWithFlags(&s2, cudaStreamNonBlocking);
    cudaEvent_t ev_fork, ev_scan, ev_join;
    cudaEventCreateWithFlags(&ev_fork, cudaEventDisableTiming);
    cudaEventCreateWithFlags(&ev_scan, cudaEventDisableTiming);
    cudaEventCreateWithFlags(&ev_join, cudaEventDisableTiming);

    cudaEventRecord(ev_fork, 0);
    cudaStreamWaitEvent(s2, ev_fork, 0);

    // side stream: memset deg/ready -> count -> scan (-> ev_scan) -> fill (-> ev_join)
    cudaMemsetAsync(deg_ptr, 0, (size_t)n * sizeof(int), s2);
    cudaMemsetAsync(ready_ptr, 0, sizeof(int), s2);
    count_deg_kernel<<<eb4, 256, 0, s2>>>(dst, E);
    scan_fused_kernel<<<nb, SCAN_B, 0, s2>>>(n, E);
    cudaEventRecord(ev_scan, s2);
    fill_edges_kernel<<<eb4, 256, 0, s2>>>(src, dst, E);
    cudaEventRecord(ev_join, s2);

    // main stream: layer-1 projection (unscaled), concurrent with CSR build
    gemm128_kernel<IN_CH, false><<<gemm_blocks, 128>>>(x, W1, P, n);

    // scale P by dinv (needs scan only) — overlaps fill_edges
    cudaStreamWaitEvent(0, ev_scan, 0);
    scale_P_kernel<<<(n * 8 + 255) / 256, 256>>>(P, n);

    // aggregate layer 1 (needs fill)
    cudaStreamWaitEvent(0, ev_join, 0);
    spmm64_kernel<true><<<spmm_blocks, 256>>>(P, b1, H, n);

    // layer 2: project with dinv folded into epilogue, aggregate
    gemm128_kernel<HID, true><<<gemm_blocks, 128>>>(H, W2, P, n);
    spmm64_kernel<false><<<spmm_blocks, 256>>>(P, b2, out, n);
}

// round 8
// speedup vs baseline: 1.1285x; 1.1285x over previous
#include <cuda_runtime.h>
#include <cuda_fp16.h>
#include <cstddef>

#define N_NODES_MAX 50000
#define N_EDGES_MAX 800000
#define IN_CH 128
#define HID 64
#define SCAN_B 1024

// ---------------- device scratch (no allocation allowed) ----------------
__device__ int    g_deg[N_NODES_MAX];
__device__ int    g_cursor[N_NODES_MAX];
__device__ int    g_row[N_NODES_MAX + 1];
__device__ float  g_dinv[N_NODES_MAX];
__device__ int    g_col[N_EDGES_MAX];          // src ids grouped by dst
__device__ int    g_bsum[(N_NODES_MAX + SCAN_B - 1) / SCAN_B + 1];
__device__ int    g_ready;                     // lookback counter (memset to 0)
__device__ __half g_P[N_NODES_MAX * 64];       // fp16 projection buffer (both layers)
__device__ float  g_H[N_NODES_MAX * 64];       // fp32 hidden activations

// ---------------- CSR build ----------------
// 2 edges/thread: atomics are latency-bound -> maximize resident warps
__global__ void count_deg_kernel(const int* __restrict__ dst, int n_edges) {
    int i0 = (blockIdx.x * blockDim.x + threadIdx.x) * 2;
    if (i0 + 2 <= n_edges) {
        int2 a = *reinterpret_cast<const int2*>(dst + i0);
        atomicAdd(&g_deg[a.x], 1);
        atomicAdd(&g_deg[a.y], 1);
    } else if (i0 < n_edges) {
        atomicAdd(&g_deg[dst[i0]], 1);
    }
}

__device__ __forceinline__ int block_scan_incl(int v, int* warp_sums) {
    int lane = threadIdx.x & 31;
    int wid = threadIdx.x >> 5;
    int x = v;
    #pragma unroll
    for (int off = 1; off < 32; off <<= 1) {
        int y = __shfl_up_sync(0xFFFFFFFFu, x, off);
        if (lane >= off) x += y;
    }
    if (lane == 31) warp_sums[wid] = x;
    __syncthreads();
    if (wid == 0) {
        int w = warp_sums[lane];
        #pragma unroll
        for (int off = 1; off < 32; off <<= 1) {
            int y = __shfl_up_sync(0xFFFFFFFFu, w, off);
            if (lane >= off) w += y;
        }
        warp_sums[lane] = w;
    }
    __syncthreads();
    return x + ((wid > 0) ? warp_sums[wid - 1] : 0);
}

// Single-pass scan with grid-resident counter wait (49 blocks << 148 SMs).
__global__ void __launch_bounds__(SCAN_B) scan_fused_kernel(int n, int E) {
    __shared__ int warp_sums[32];
    __shared__ int s_off;
    int b = blockIdx.x;
    int i = b * SCAN_B + threadIdx.x;
    int v = (i < n) ? g_deg[i] : 0;
    int incl = block_scan_incl(v, warp_sums);

    if (threadIdx.x == 0) {
        g_bsum[b] = warp_sums[31];
        __threadfence();
        atomicAdd(&g_ready, 1);
        while (atomicAdd(&g_ready, 0) < (int)gridDim.x) {}
        __threadfence();
        int s = 0;
        for (int j = 0; j < b; j++) s += g_bsum[j];
        s_off = s;
    }
    __syncthreads();

    if (i < n) {
        int r = incl - v + s_off;
        g_row[i] = r;
        g_cursor[i] = r;
        g_dinv[i] = rsqrtf((float)v + 1.0f);  // deg incl. self-loop
    }
    if (b == 0 && threadIdx.x == 0) g_row[n] = E;
}

__global__ void fill_edges_kernel(const int* __restrict__ src,
                                  const int* __restrict__ dst, int n_edges) {
    int i0 = (blockIdx.x * blockDim.x + threadIdx.x) * 2;
    if (i0 + 2 <= n_edges) {
        int2 d = *reinterpret_cast<const int2*>(dst + i0);
        int2 s = *reinterpret_cast<const int2*>(src + i0);
        int p0 = atomicAdd(&g_cursor[d.x], 1);
        int p1 = atomicAdd(&g_cursor[d.y], 1);
        g_col[p0] = s.x;
        g_col[p1] = s.y;
    } else if (i0 < n_edges) {
        int p = atomicAdd(&g_cursor[dst[i0]], 1);
        g_col[p] = src[i0];
    }
}

// scale P rows by dinv: P'[i] = dinv[i] * P[i]
__global__ void scale_P_kernel(__half* __restrict__ P, int n) {
    int t = blockIdx.x * blockDim.x + threadIdx.x;
    int node = t >> 3;
    if (node >= n) return;
    int l = t & 7;
    float di = g_dinv[node];
    uint4 v = reinterpret_cast<uint4*>(P)[(size_t)node * 8 + l];
    __half2* hp = reinterpret_cast<__half2*>(&v);
    #pragma unroll
    for (int j = 0; j < 4; j++) {
        float2 f = __half22float2(hp[j]);
        hp[j] = __floats2half2_rn(f.x * di, f.y * di);
    }
    reinterpret_cast<uint4*>(P)[(size_t)node * 8 + l] = v;
}

// ---------------- tf32 tensor-core GEMM: Y[n,64](fp16) = (X[n,K] @ W[K,64]) * (dinv?) ----------------
__device__ __forceinline__ unsigned f2tf32(float f) {
    unsigned r;
    asm("cvt.rna.tf32.f32 %0, %1;" : "=r"(r) : "f"(f));
    return r;
}

__device__ __forceinline__ void mma_tf32(float* c, unsigned a0, unsigned a1,
                                         unsigned a2, unsigned a3,
                                         unsigned b0, unsigned b1) {
    asm volatile(
        "mma.sync.aligned.m16n8k8.row.col.f32.tf32.tf32.f32 "
        "{%0,%1,%2,%3}, {%4,%5,%6,%7}, {%8,%9}, {%0,%1,%2,%3};"
        : "+f"(c[0]), "+f"(c[1]), "+f"(c[2]), "+f"(c[3])
        : "r"(a0), "r"(a1), "r"(a2), "r"(a3), "r"(b0), "r"(b1));
}

// Block: 256 threads (8 warps), tile 128 rows x 64 cols.
// Warp w: rows [w*16, w*16+16), all 64 cols as 8 m16n8 accumulators.
// Xs stride 40 (== 8 mod 32): A-frag LDS conflict-free. Ws stride 72 (== 8 mod 32): B-frag conflict-free.
template <int K, bool SCALE_DINV>
__global__ void __launch_bounds__(256) gemm_tc_kernel(const float* __restrict__ X,
                                                      const float* __restrict__ W,
                                                      __half* __restrict__ Y, int n) {
    const int KC = 32;
    __shared__ unsigned Xs[128][40];   // [row][k], tf32 bits
    __shared__ unsigned Ws[KC][72];    // [k][n],  tf32 bits

    int t = threadIdx.x;
    int lane = t & 31;
    int warp = t >> 5;          // 0..7
    int row0 = blockIdx.x * 128;
    int m_w = warp * 16;
    int g = lane >> 2;          // 0..7
    int tig = lane & 3;         // 0..3

    float c[8][4];
    #pragma unroll
    for (int j = 0; j < 8; j++)
        #pragma unroll
        for (int q = 0; q < 4; q++) c[j][q] = 0.0f;

    for (int kc = 0; kc < K; kc += KC) {
        // X chunk: 128 rows x 32 k = 1024 float4 -> 4 per thread (coalesced 128B/row)
        #pragma unroll
        for (int u = 0; u < 4; u++) {
            int idx = t + u * 256;
            int r = idx >> 3;        // 0..127
            int q = idx & 7;         // float4 along k
            int row = row0 + r;
            if (row >= n) row = n - 1;
            float4 v = *reinterpret_cast<const float4*>(X + (size_t)row * K + kc + q * 4);
            unsigned* dstp = &Xs[r][q * 4];
            dstp[0] = f2tf32(v.x);
            dstp[1] = f2tf32(v.y);
            dstp[2] = f2tf32(v.z);
            dstp[3] = f2tf32(v.w);
        }
        // W chunk: 32 k x 64 n = 512 float4 -> 2 per thread
        #pragma unroll
        for (int u = 0; u < 2; u++) {
            int idx = t + u * 256;
            int kk = idx >> 4;       // 0..31
            int q = idx & 15;        // float4 along n
            float4 v = *reinterpret_cast<const float4*>(W + (size_t)(kc + kk) * 64 + q * 4);
            unsigned* dstp = &Ws[kk][q * 4];
            dstp[0] = f2tf32(v.x);
            dstp[1] = f2tf32(v.y);
            dstp[2] = f2tf32(v.z);
            dstp[3] = f2tf32(v.w);
        }
        __syncthreads();

        #pragma unroll
        for (int s = 0; s < KC / 8; s++) {
            int k0 = s * 8;
            unsigned a0 = Xs[m_w + g][k0 + tig];
            unsigned a1 = Xs[m_w + g + 8][k0 + tig];
            unsigned a2 = Xs[m_w + g][k0 + tig + 4];
            unsigned a3 = Xs[m_w + g + 8][k0 + tig + 4];
            #pragma unroll
            for (int j = 0; j < 8; j++) {
                unsigned b0 = Ws[k0 + tig][j * 8 + g];
                unsigned b1 = Ws[k0 + tig + 4][j * 8 + g];
                mma_tf32(c[j], a0, a1, a2, a3, b0, b1);
            }
        }
        __syncthreads();
    }

    // epilogue: c[j] = {(g, 2tig), (g, 2tig+1), (g+8, 2tig), (g+8, 2tig+1)} of tile (m_w, 8j)
    int r0 = row0 + m_w + g;
    int r1 = r0 + 8;
    float s0 = 1.0f, s1 = 1.0f;
    if (SCALE_DINV) {
        s0 = (r0 < n) ? g_dinv[r0] : 0.0f;
        s1 = (r1 < n) ? g_dinv[r1] : 0.0f;
    }
    #pragma unroll
    for (int j = 0; j < 8; j++) {
        int colb = j * 8 + 2 * tig;
        if (r0 < n)
            *reinterpret_cast<__half2*>(Y + (size_t)r0 * 64 + colb) =
                __floats2half2_rn(c[j][0] * s0, c[j][1] * s0);
        if (r1 < n)
            *reinterpret_cast<__half2*>(Y + (size_t)r1 * 64 + colb) =
                __floats2half2_rn(c[j][2] * s1, c[j][3] * s1);
    }
}

// ---------------- aggregation on pre-scaled P': out = dinv[d]*(ΣP'[src] + P'[d]) + b ----------------
template <bool RELU>
__global__ void __launch_bounds__(256) spmm64_kernel(const __half* __restrict__ P,
                                                     const float* __restrict__ bias,
                                                     float* __restrict__ Y, int n) {
    int t = blockIdx.x * blockDim.x + threadIdx.x;
    int node = t >> 3;
    if (node >= n) return;
    int l = t & 7;

    const uint4* Pv = reinterpret_cast<const uint4*>(P);
    float di = g_dinv[node];

    float acc[8];
    {
        uint4 v = Pv[(size_t)node * 8 + l];   // self-loop term P'[node]
        const __half2* hp = reinterpret_cast<const __half2*>(&v);
        #pragma unroll
        for (int j = 0; j < 4; j++) {
            float2 f = __half22float2(hp[j]);
            acc[2 * j]     = f.x;
            acc[2 * j + 1] = f.y;
        }
    }

    int e = g_row[node];
    int end = g_row[node + 1];
    for (; e + 4 <= end; e += 4) {
        int s0 = g_col[e], s1 = g_col[e + 1], s2 = g_col[e + 2], s3 = g_col[e + 3];
        uint4 v0 = Pv[(size_t)s0 * 8 + l];
        uint4 v1 = Pv[(size_t)s1 * 8 + l];
        uint4 v2 = Pv[(size_t)s2 * 8 + l];
        uint4 v3 = Pv[(size_t)s3 * 8 + l];
        const __half2* h0 = reinterpret_cast<const __half2*>(&v0);
        const __half2* h1 = reinterpret_cast<const __half2*>(&v1);
        const __half2* h2 = reinterpret_cast<const __half2*>(&v2);
        const __half2* h3 = reinterpret_cast<const __half2*>(&v3);
        #pragma unroll
        for (int j = 0; j < 4; j++) {
            float2 f0 = __half22float2(h0[j]);
            float2 f1 = __half22float2(h1[j]);
            float2 f2 = __half22float2(h2[j]);
            float2 f3 = __half22float2(h3[j]);
            acc[2 * j]     += (f0.x + f1.x) + (f2.x + f3.x);
            acc[2 * j + 1] += (f0.y + f1.y) + (f2.y + f3.y);
        }
    }
    for (; e < end; e++) {
        int s0 = g_col[e];
        uint4 v0 = Pv[(size_t)s0 * 8 + l];
        const __half2* h0 = reinterpret_cast<const __half2*>(&v0);
        #pragma unroll
        for (int j = 0; j < 4; j++) {
            float2 f0 = __half22float2(h0[j]);
            acc[2 * j]     += f0.x;
            acc[2 * j + 1] += f0.y;
        }
    }

    float4 b0 = reinterpret_cast<const float4*>(bias)[l * 2];
    float4 b1 = reinterpret_cast<const float4*>(bias)[l * 2 + 1];
    acc[0] = acc[0] * di + b0.x; acc[1] = acc[1] * di + b0.y;
    acc[2] = acc[2] * di + b0.z; acc[3] = acc[3] * di + b0.w;
    acc[4] = acc[4] * di + b1.x; acc[5] = acc[5] * di + b1.y;
    acc[6] = acc[6] * di + b1.z; acc[7] = acc[7] * di + b1.w;
    if (RELU) {
        #pragma unroll
        for (int j = 0; j < 8; j++) acc[j] = fmaxf(acc[j], 0.0f);
    }
    float4* Yo = reinterpret_cast<float4*>(Y + (size_t)node * 64 + l * 8);
    Yo[0] = make_float4(acc[0], acc[1], acc[2], acc[3]);
    Yo[1] = make_float4(acc[4], acc[5], acc[6], acc[7]);
}

// ---------------- launcher ----------------
extern "C" void kernel_launch(void* const* d_in, const int* in_sizes, int n_in,
                              void* d_out, int out_size) {
    const float* x  = (const float*)d_in[0];       // [n, 128]
    const int*   ei = (const int*)d_in[1];         // [2, E]
    const float* W1 = (const float*)d_in[2];       // [128, 64]
    const float* b1 = (const float*)d_in[3];       // [64]
    const float* W2 = (const float*)d_in[4];       // [64, 64]
    const float* b2 = (const float*)d_in[5];       // [64]
    float* out = (float*)d_out;                    // [n, 64]

    int n = in_sizes[0] / IN_CH;
    int E = in_sizes[1] / 2;
    const int* src = ei;
    const int* dst = ei + E;

    void* p;
    cudaGetSymbolAddress(&p, g_P);
    __half* P = (__half*)p;
    cudaGetSymbolAddress(&p, g_H);
    float* H = (float*)p;
    void* deg_ptr;
    cudaGetSymbolAddress(&deg_ptr, g_deg);
    void* ready_ptr;
    cudaGetSymbolAddress(&ready_ptr, g_ready);

    int nb = (n + SCAN_B - 1) / SCAN_B;
    int eb2 = (E + 2 * 256 - 1) / (2 * 256);
    int spmm_blocks = (n * 8 + 255) / 256;
    int gemm_blocks = (n + 127) / 128;

    // Fork side stream: CSR build overlaps GEMM1. (Host objects leak by design;
    // destroying capture-participating streams/events mid-capture is illegal.)
    cudaStream_t s2;
    cudaStreamCreateWithFlags(&s2, cudaStreamNonBlocking);
    cudaEvent_t ev_fork, ev_scan, ev_join;
    cudaEventCreateWithFlags(&ev_fork, cudaEventDisableTiming);
    cudaEventCreateWithFlags(&ev_scan, cudaEventDisableTiming);
    cudaEventCreateWithFlags(&ev_join, cudaEventDisableTiming);

    cudaEventRecord(ev_fork, 0);
    cudaStreamWaitEvent(s2, ev_fork, 0);

    // side stream: memset deg/ready -> count -> scan (-> ev_scan) -> fill (-> ev_join)
    cudaMemsetAsync(deg_ptr, 0, (size_t)n * sizeof(int), s2);
    cudaMemsetAsync(ready_ptr, 0, sizeof(int), s2);
    count_deg_kernel<<<eb2, 256, 0, s2>>>(dst, E);
    scan_fused_kernel<<<nb, SCAN_B, 0, s2>>>(n, E);
    cudaEventRecord(ev_scan, s2);
    fill_edges_kernel<<<eb2, 256, 0, s2>>>(src, dst, E);
    cudaEventRecord(ev_join, s2);

    // main stream: layer-1 projection (tensor cores), concurrent with CSR build
    gemm_tc_kernel<IN_CH, false><<<gemm_blocks, 256>>>(x, W1, P, n);

    // scale P by dinv (needs scan only) — overlaps fill_edges
    cudaStreamWaitEvent(0, ev_scan, 0);
    scale_P_kernel<<<(n * 8 + 255) / 256, 256>>>(P, n);

    // aggregate layer 1 (needs fill)
    cudaStreamWaitEvent(0, ev_join, 0);
    spmm64_kernel<true><<<spmm_blocks, 256>>>(P, b1, H, n);

    // layer 2: project with dinv folded into epilogue, aggregate
    gemm_tc_kernel<HID, true><<<gemm_blocks, 256>>>(H, W2, P, n);
    spmm64_kernel<false><<<spmm_blocks, 256>>>(P, b2, out, n);
}

// round 11
// speedup vs baseline: 1.1707x; 1.0374x over previous
#include <cuda_runtime.h>
#include <cuda_fp16.h>
#include <cstddef>
#include <cstdint>

#define N_NODES_MAX 50000
#define N_EDGES_MAX 800000
#define IN_CH 128
#define HID 64
#define SCAN_B 1024

// ---------------- device scratch (no allocation allowed) ----------------
__device__ int    g_deg[N_NODES_MAX];
__device__ int    g_row[N_NODES_MAX + 1];
__device__ float  g_dinv[N_NODES_MAX];
__device__ int    g_col[N_EDGES_MAX];          // src ids grouped by dst
__device__ int    g_slot[N_EDGES_MAX];         // per-edge rank within its dst bucket
__device__ int    g_bsum[(N_NODES_MAX + SCAN_B - 1) / SCAN_B + 1];
__device__ int    g_ready;                     // lookback counter
__device__ __half g_P[N_NODES_MAX * 64];       // fp16 projection buffer (both layers)
__device__ float  g_H[N_NODES_MAX * 64];       // fp32 hidden activations

// ---------------- cp.async helpers ----------------
__device__ __forceinline__ void cp_async16(uint32_t smem_addr, const void* gptr) {
    asm volatile("cp.async.cg.shared.global [%0], [%1], 16;\n"
                 :: "r"(smem_addr), "l"(gptr));
}
__device__ __forceinline__ void cp_commit() {
    asm volatile("cp.async.commit_group;\n");
}
template <int N>
__device__ __forceinline__ void cp_wait() {
    asm volatile("cp.async.wait_group %0;\n" :: "n"(N));
}

// ---------------- CSR build ----------------
// count: 4 edges/thread, atomics WITH return -> also records the edge's slot
__global__ void count_deg_kernel(const int* __restrict__ dst, int n_edges) {
    if (blockIdx.x == 0 && threadIdx.x == 0) g_ready = 0;  // for scan (next launch)
    int i0 = (blockIdx.x * blockDim.x + threadIdx.x) * 4;
    if (i0 + 4 <= n_edges) {
        int4 d = *reinterpret_cast<const int4*>(dst + i0);
        int4 sl;
        sl.x = atomicAdd(&g_deg[d.x], 1);
        sl.y = atomicAdd(&g_deg[d.y], 1);
        sl.z = atomicAdd(&g_deg[d.z], 1);
        sl.w = atomicAdd(&g_deg[d.w], 1);
        *reinterpret_cast<int4*>(g_slot + i0) = sl;
    } else {
        for (int j = 0; j < 4 && i0 + j < n_edges; j++)
            g_slot[i0 + j] = atomicAdd(&g_deg[dst[i0 + j]], 1);
    }
}

__device__ __forceinline__ int block_scan_incl(int v, int* warp_sums) {
    int lane = threadIdx.x & 31;
    int wid = threadIdx.x >> 5;
    int x = v;
    #pragma unroll
    for (int off = 1; off < 32; off <<= 1) {
        int y = __shfl_up_sync(0xFFFFFFFFu, x, off);
        if (lane >= off) x += y;
    }
    if (lane == 31) warp_sums[wid] = x;
    __syncthreads();
    if (wid == 0) {
        int w = warp_sums[lane];
        #pragma unroll
        for (int off = 1; off < 32; off <<= 1) {
            int y = __shfl_up_sync(0xFFFFFFFFu, w, off);
            if (lane >= off) w += y;
        }
        warp_sums[lane] = w;
    }
    __syncthreads();
    return x + ((wid > 0) ? warp_sums[wid - 1] : 0);
}

// Single-pass scan with grid-resident counter wait (49 blocks << 148 SMs).
__global__ void __launch_bounds__(SCAN_B) scan_fused_kernel(int n, int E) {
    __shared__ int warp_sums[32];
    __shared__ int s_off;
    int b = blockIdx.x;
    int i = b * SCAN_B + threadIdx.x;
    int v = (i < n) ? g_deg[i] : 0;
    int incl = block_scan_incl(v, warp_sums);

    if (threadIdx.x == 0) {
        g_bsum[b] = warp_sums[31];
        __threadfence();
        atomicAdd(&g_ready, 1);
        while (atomicAdd(&g_ready, 0) < (int)gridDim.x) {}
        __threadfence();
        int s = 0;
        for (int j = 0; j < b; j++) s += g_bsum[j];
        s_off = s;
    }
    __syncthreads();

    if (i < n) {
        g_row[i] = incl - v + s_off;
        g_dinv[i] = rsqrtf((float)v + 1.0f);  // deg incl. self-loop
    }
    if (b == 0 && threadIdx.x == 0) g_row[n] = E;
}

// fill: NO atomics — p = row[dst] + slot[i]
__global__ void fill_edges_kernel(const int* __restrict__ src,
                                  const int* __restrict__ dst, int n_edges) {
    int i0 = (blockIdx.x * blockDim.x + threadIdx.x) * 4;
    if (i0 + 4 <= n_edges) {
        int4 d = *reinterpret_cast<const int4*>(dst + i0);
        int4 s = *reinterpret_cast<const int4*>(src + i0);
        int4 sl = *reinterpret_cast<const int4*>(g_slot + i0);
        g_col[g_row[d.x] + sl.x] = s.x;
        g_col[g_row[d.y] + sl.y] = s.y;
        g_col[g_row[d.z] + sl.z] = s.z;
        g_col[g_row[d.w] + sl.w] = s.w;
    } else {
        for (int j = 0; j < 4 && i0 + j < n_edges; j++)
            g_col[g_row[dst[i0 + j]] + g_slot[i0 + j]] = src[i0 + j];
    }
}

// scale P rows by dinv: P'[i] = dinv[i] * P[i]
__global__ void scale_P_kernel(__half* __restrict__ P, int n) {
    int t = blockIdx.x * blockDim.x + threadIdx.x;
    int node = t >> 3;
    if (node >= n) return;
    int l = t & 7;
    float di = g_dinv[node];
    uint4 v = reinterpret_cast<uint4*>(P)[(size_t)node * 8 + l];
    __half2* hp = reinterpret_cast<__half2*>(&v);
    #pragma unroll
    for (int j = 0; j < 4; j++) {
        float2 f = __half22float2(hp[j]);
        hp[j] = __floats2half2_rn(f.x * di, f.y * di);
    }
    reinterpret_cast<uint4*>(P)[(size_t)node * 8 + l] = v;
}

// ---------------- tf32 tensor-core GEMM with cp.async double buffering ----------------
__device__ __forceinline__ unsigned cvt_tf32(unsigned bits) {
    unsigned r;
    asm("cvt.rna.tf32.f32 %0, %1;" : "=r"(r) : "f"(__uint_as_float(bits)));
    return r;
}

__device__ __forceinline__ void mma_tf32(float* c, unsigned a0, unsigned a1,
                                         unsigned a2, unsigned a3,
                                         unsigned b0, unsigned b1) {
    asm volatile(
        "mma.sync.aligned.m16n8k8.row.col.f32.tf32.tf32.f32 "
        "{%0,%1,%2,%3}, {%4,%5,%6,%7}, {%8,%9}, {%0,%1,%2,%3};"
        : "+f"(c[0]), "+f"(c[1]), "+f"(c[2]), "+f"(c[3])
        : "r"(a0), "r"(a1), "r"(a2), "r"(a3), "r"(b0), "r"(b1));
}

// Dynamic smem layout: Xs[2][128][40] then Ws[2][32][72]  (59392 B total)
#define XS_STRIDE 40
#define WS_STRIDE 72
#define XS_WORDS (2 * 128 * XS_STRIDE)
#define SMEM_GEMM_BYTES ((XS_WORDS + 2 * 32 * WS_STRIDE) * 4)

// 256 threads (8 warps), tile 128 rows x 64 cols, KC=32, 2-stage cp.async pipeline.
// fp32 bits staged via cp.async; cvt.rna.tf32 applied on the register fragments
// (round-to-nearest tf32 => same numerics as round-7's converting loader).
// Xs stride 40 (==8 mod 32) and Ws stride 72 (==8 mod 32): conflict-free frag loads.
template <int K, bool SCALE_DINV>
__global__ void __launch_bounds__(256) gemm_tc_kernel(const float* __restrict__ X,
                                                      const float* __restrict__ W,
                                                      __half* __restrict__ Y, int n) {
    const int KC = 32;
    const int NC = K / KC;
    extern __shared__ unsigned smem_dyn[];
    unsigned* Xs = smem_dyn;                 // Xs[st][row][k]
    unsigned* Ws = smem_dyn + XS_WORDS;      // Ws[st][k][nn]

    int t = threadIdx.x;
    int lane = t & 31;
    int warp = t >> 5;          // 0..7
    int row0 = blockIdx.x * 128;
    int m_w = warp * 16;
    int g = lane >> 2;          // 0..7
    int tig = lane & 3;         // 0..3

    // per-thread load coordinates
    int xr[4], xq[4];
    const float* xsrc[4];
    #pragma unroll
    for (int u = 0; u < 4; u++) {
        int idx = t + u * 256;
        xr[u] = idx >> 3;        // 0..127
        xq[u] = idx & 7;         // float4 along k
        int row = row0 + xr[u];
        if (row >= n) row = n - 1;
        xsrc[u] = X + (size_t)row * K + xq[u] * 4;
    }
    int wk[2], wq[2];
    #pragma unroll
    for (int u = 0; u < 2; u++) {
        int idx = t + u * 256;
        wk[u] = idx >> 4;        // 0..31
        wq[u] = idx & 15;        // float4 along n
    }

    auto load_chunk = [&](int st, int kc) {
        #pragma unroll
        for (int u = 0; u < 4; u++)
            cp_async16((uint32_t)__cvta_generic_to_shared(
                           &Xs[st * 128 * XS_STRIDE + xr[u] * XS_STRIDE + xq[u] * 4]),
                       xsrc[u] + kc);
        #pragma unroll
        for (int u = 0; u < 2; u++)
            cp_async16((uint32_t)__cvta_generic_to_shared(
                           &Ws[st * 32 * WS_STRIDE + wk[u] * WS_STRIDE + wq[u] * 4]),
                       W + (size_t)(kc + wk[u]) * 64 + wq[u] * 4);
        cp_commit();
    };

    float c[8][4];
    #pragma unroll
    for (int j = 0; j < 8; j++)
        #pragma unroll
        for (int q = 0; q < 4; q++) c[j][q] = 0.0f;

    load_chunk(0, 0);

    #pragma unroll
    for (int cidx = 0; cidx < NC; cidx++) {
        int buf = cidx & 1;
        if (cidx + 1 < NC) {
            load_chunk(buf ^ 1, (cidx + 1) * KC);
            cp_wait<1>();
        } else {
            cp_wait<0>();
        }
        __syncthreads();

        const unsigned* Xb = Xs + buf * 128 * XS_STRIDE;
        const unsigned* Wb = Ws + buf * 32 * WS_STRIDE;
        #pragma unroll
        for (int s = 0; s < KC / 8; s++) {
            int k0 = s * 8;
            unsigned a0 = cvt_tf32(Xb[(m_w + g) * XS_STRIDE + k0 + tig]);
            unsigned a1 = cvt_tf32(Xb[(m_w + g + 8) * XS_STRIDE + k0 + tig]);
            unsigned a2 = cvt_tf32(Xb[(m_w + g) * XS_STRIDE + k0 + tig + 4]);
            unsigned a3 = cvt_tf32(Xb[(m_w + g + 8) * XS_STRIDE + k0 + tig + 4]);
            #pragma unroll
            for (int j = 0; j < 8; j++) {
                unsigned b0 = cvt_tf32(Wb[(k0 + tig) * WS_STRIDE + j * 8 + g]);
                unsigned b1 = cvt_tf32(Wb[(k0 + tig + 4) * WS_STRIDE + j * 8 + g]);
                mma_tf32(c[j], a0, a1, a2, a3, b0, b1);
            }
        }
        __syncthreads();
    }

    // epilogue
    int r0 = row0 + m_w + g;
    int r1 = r0 + 8;
    float s0 = 1.0f, s1 = 1.0f;
    if (SCALE_DINV) {
        s0 = (r0 < n) ? g_dinv[r0] : 0.0f;
        s1 = (r1 < n) ? g_dinv[r1] : 0.0f;
    }
    #pragma unroll
    for (int j = 0; j < 8; j++) {
        int colb = j * 8 + 2 * tig;
        if (r0 < n)
            *reinterpret_cast<__half2*>(Y + (size_t)r0 * 64 + colb) =
                __floats2half2_rn(c[j][0] * s0, c[j][1] * s0);
        if (r1 < n)
            *reinterpret_cast<__half2*>(Y + (size_t)r1 * 64 + colb) =
                __floats2half2_rn(c[j][2] * s1, c[j][3] * s1);
    }
}

// ---------------- aggregation on pre-scaled P': out = dinv[d]*(ΣP'[src] + P'[d]) + b ----------------
template <bool RELU>
__global__ void __launch_bounds__(256) spmm64_kernel(const __half* __restrict__ P,
                                                     const float* __restrict__ bias,
                                                     float* __restrict__ Y, int n) {
    int t = blockIdx.x * blockDim.x + threadIdx.x;
    int node = t >> 3;
    if (node >= n) return;
    int l = t & 7;

    const uint4* Pv = reinterpret_cast<const uint4*>(P);
    float di = g_dinv[node];

    float acc[8];
    {
        uint4 v = Pv[(size_t)node * 8 + l];   // self-loop term P'[node]
        const __half2* hp = reinterpret_cast<const __half2*>(&v);
        #pragma unroll
        for (int j = 0; j < 4; j++) {
            float2 f = __half22float2(hp[j]);
            acc[2 * j]     = f.x;
            acc[2 * j + 1] = f.y;
        }
    }

    int e = g_row[node];
    int end = g_row[node + 1];
    for (; e + 4 <= end; e += 4) {
        int s0 = g_col[e], s1 = g_col[e + 1], s2 = g_col[e + 2], s3 = g_col[e + 3];
        uint4 v0 = Pv[(size_t)s0 * 8 + l];
        uint4 v1 = Pv[(size_t)s1 * 8 + l];
        uint4 v2 = Pv[(size_t)s2 * 8 + l];
        uint4 v3 = Pv[(size_t)s3 * 8 + l];
        const __half2* h0 = reinterpret_cast<const __half2*>(&v0);
        const __half2* h1 = reinterpret_cast<const __half2*>(&v1);
        const __half2* h2 = reinterpret_cast<const __half2*>(&v2);
        const __half2* h3 = reinterpret_cast<const __half2*>(&v3);
        #pragma unroll
        for (int j = 0; j < 4; j++) {
            float2 f0 = __half22float2(h0[j]);
            float2 f1 = __half22float2(h1[j]);
            float2 f2 = __half22float2(h2[j]);
            float2 f3 = __half22float2(h3[j]);
            acc[2 * j]     += (f0.x + f1.x) + (f2.x + f3.x);
            acc[2 * j + 1] += (f0.y + f1.y) + (f2.y + f3.y);
        }
    }
    for (; e < end; e++) {
        int s0 = g_col[e];
        uint4 v0 = Pv[(size_t)s0 * 8 + l];
        const __half2* h0 = reinterpret_cast<const __half2*>(&v0);
        #pragma unroll
        for (int j = 0; j < 4; j++) {
            float2 f0 = __half22float2(h0[j]);
            acc[2 * j]     += f0.x;
            acc[2 * j + 1] += f0.y;
        }
    }

    float4 b0 = reinterpret_cast<const float4*>(bias)[l * 2];
    float4 b1 = reinterpret_cast<const float4*>(bias)[l * 2 + 1];
    acc[0] = acc[0] * di + b0.x; acc[1] = acc[1] * di + b0.y;
    acc[2] = acc[2] * di + b0.z; acc[3] = acc[3] * di + b0.w;
    acc[4] = acc[4] * di + b1.x; acc[5] = acc[5] * di + b1.y;
    acc[6] = acc[6] * di + b1.z; acc[7] = acc[7] * di + b1.w;
    if (RELU) {
        #pragma unroll
        for (int j = 0; j < 8; j++) acc[j] = fmaxf(acc[j], 0.0f);
    }
    float4* Yo = reinterpret_cast<float4*>(Y + (size_t)node * 64 + l * 8);
    Yo[0] = make_float4(acc[0], acc[1], acc[2], acc[3]);
    Yo[1] = make_float4(acc[4], acc[5], acc[6], acc[7]);
}

// ---------------- launcher ----------------
extern "C" void kernel_launch(void* const* d_in, const int* in_sizes, int n_in,
                              void* d_out, int out_size) {
    const float* x  = (const float*)d_in[0];       // [n, 128]
    const int*   ei = (const int*)d_in[1];         // [2, E]
    const float* W1 = (const float*)d_in[2];       // [128, 64]
    const float* b1 = (const float*)d_in[3];       // [64]
    const float* W2 = (const float*)d_in[4];       // [64, 64]
    const float* b2 = (const float*)d_in[5];       // [64]
    float* out = (float*)d_out;                    // [n, 64]

    int n = in_sizes[0] / IN_CH;
    int E = in_sizes[1] / 2;
    const int* src = ei;
    const int* dst = ei + E;

    void* p;
    cudaGetSymbolAddress(&p, g_P);
    __half* P = (__half*)p;
    cudaGetSymbolAddress(&p, g_H);
    float* H = (float*)p;
    void* deg_ptr;
    cudaGetSymbolAddress(&deg_ptr, g_deg);

    // allow >48KB dynamic smem for the GEMM kernels (host attribute, no allocation)
    cudaFuncSetAttribute(gemm_tc_kernel<IN_CH, false>,
                         cudaFuncAttributeMaxDynamicSharedMemorySize, SMEM_GEMM_BYTES);
    cudaFuncSetAttribute(gemm_tc_kernel<HID, true>,
                         cudaFuncAttributeMaxDynamicSharedMemorySize, SMEM_GEMM_BYTES);

    int nb = (n + SCAN_B - 1) / SCAN_B;
    int eb4 = (E + 4 * 256 - 1) / (4 * 256);
    int spmm_blocks = (n * 8 + 255) / 256;
    int gemm_blocks = (n + 127) / 128;

    // Fork side stream: CSR build overlaps GEMM1. (Host objects leak by design;
    // destroying capture-participating streams/events mid-capture is illegal.)
    cudaStream_t s2;
    cudaStreamCreateWithFlags(&s2, cudaStreamNonBlocking);
    cudaEvent_t ev_fork, ev_scan, ev_join;
    cudaEventCreateWithFlags(&ev_fork, cudaEventDisableTiming);
    cudaEventCreateWithFlags(&ev_scan, cudaEventDisableTiming);
    cudaEventCreateWithFlags(&ev_join, cudaEventDisableTiming);

    cudaEventRecord(ev_fork, 0);
    cudaStreamWaitEvent(s2, ev_fork, 0);

    // side stream: memset deg -> count(+slot, resets ready) -> scan -> fill (no atomics)
    cudaMemsetAsync(deg_ptr, 0, (size_t)n * sizeof(int), s2);
    count_deg_kernel<<<eb4, 256, 0, s2>>>(dst, E);
    scan_fused_kernel<<<nb, SCAN_B, 0, s2>>>(n, E);
    cudaEventRecord(ev_scan, s2);
    fill_edges_kernel<<<eb4, 256, 0, s2>>>(src, dst, E);
    cudaEventRecord(ev_join, s2);

    // main stream: layer-1 projection (tensor cores), concurrent with CSR build
    gemm_tc_kernel<IN_CH, false><<<gemm_blocks, 256, SMEM_GEMM_BYTES>>>(x, W1, P, n);

    // scale P by dinv (needs scan only) — overlaps fill_edges
    cudaStreamWaitEvent(0, ev_scan, 0);
    scale_P_kernel<<<(n * 8 + 255) / 256, 256>>>(P, n);

    // aggregate layer 1 (needs fill)
    cudaStreamWaitEvent(0, ev_join, 0);
    spmm64_kernel<true><<<spmm_blocks, 256>>>(P, b1, H, n);

    // layer 2: project with dinv folded into epilogue, aggregate
    gemm_tc_kernel<HID, true><<<gemm_blocks, 256, SMEM_GEMM_BYTES>>>(H, W2, P, n);
    spmm64_kernel<false><<<spmm_blocks, 256>>>(P, b2, out, n);
}